// round 10
// baseline (speedup 1.0000x reference)
#include <cuda_runtime.h>
#include <cuda_bf16.h>
#include <cstdint>

#define NN 8192
#define FI 128
#define FO 64
#define LRALPHA 0.2f
#define KSPLIT 8
#define MT 128          // M rows per CTA
#define KT 64           // j per K-tile
#define NBF 64          // B rows (features only; den handled in build)
#define STRIDE_OUT 72

// ---------------- device scratch ----------------
__device__ float g_h[NN*FO];
__device__ __align__(16) float g_t[NN];
__device__ __align__(16) float g_u[NN], g_v[NN];   // fp32 exp(t), exp(a t)
__device__ float g_s[NN], g_p[NN], g_q[NN];
__device__ __align__(16) __nv_bfloat16 g_Bh[(size_t)NBF*NN];  // bf16(h)
__device__ __align__(16) __nv_bfloat16 g_Bl[(size_t)NBF*NN];  // residual
__device__ float g_num[KSPLIT][(size_t)NN*STRIDE_OUT];

// ---------------- helpers ----------------
__device__ __forceinline__ uint32_t smem_u32(const void* p) {
    uint32_t a;
    asm("{ .reg .u64 t; cvta.to.shared.u64 t, %1; cvt.u32.u64 %0, t; }" : "=r"(a) : "l"(p));
    return a;
}
#define SWZ(x) ((uint32_t)(x) ^ ((((uint32_t)(x)) >> 3) & 0x70u))

__device__ __forceinline__ void ldm_x4(uint32_t addr, uint32_t r[4]) {
    asm volatile("ldmatrix.sync.aligned.m8n8.x4.shared.b16 {%0,%1,%2,%3}, [%4];"
        : "=r"(r[0]), "=r"(r[1]), "=r"(r[2]), "=r"(r[3]) : "r"(addr));
}
__device__ __forceinline__ void mma16816(float* c, const uint32_t* a, const uint32_t* b) {
    asm("mma.sync.aligned.m16n8k16.row.col.f32.bf16.bf16.f32 "
        "{%0,%1,%2,%3}, {%4,%5,%6,%7}, {%8,%9}, {%0,%1,%2,%3};"
        : "+f"(c[0]), "+f"(c[1]), "+f"(c[2]), "+f"(c[3])
        : "r"(a[0]), "r"(a[1]), "r"(a[2]), "r"(a[3]), "r"(b[0]), "r"(b[1]));
}
__device__ __forceinline__ void cp16(uint32_t dst, const void* src) {
    asm volatile("cp.async.cg.shared.global [%0], [%1], 16;" :: "r"(dst), "l"(src) : "memory");
}
#define CP_COMMIT() asm volatile("cp.async.commit_group;" ::: "memory")
#define CP_WAIT(n)  asm volatile("cp.async.wait_group %0;" :: "n"(n) : "memory")
__device__ __forceinline__ void prefetchL1(const void* p) {
    asm volatile("prefetch.global.L1 [%0];" :: "l"(p));
}

// pack two fp32 weights into hi-bf16x2 and lo-bf16x2 (truncation split)
__device__ __forceinline__ void packpair(uint32_t& hi, uint32_t& lo, float w0, float w1) {
    uint32_t b0 = __float_as_uint(w0), b1 = __float_as_uint(w1);
    hi = __byte_perm(b0, b1, 0x7632);
    float l0 = w0 - __uint_as_float(b0 & 0xFFFF0000u);
    float l1 = w1 - __uint_as_float(b1 & 0xFFFF0000u);
    lo = __byte_perm(__float_as_uint(l0), __float_as_uint(l1), 0x7632);
}

// ---------------- kernel 1: h = x @ W  (+ fused per-row scalars) ----------------
__global__ void k_gemm_h(const float* __restrict__ x, const float* __restrict__ W,
                         const float* __restrict__ a) {
    __shared__ float sW[FI*FO];     // reused as sh[64][64]
    __shared__ float sx[64][FI];
    int tid = threadIdx.x;
    for (int i = tid; i < FI*FO; i += 256) sW[i] = W[i];
    int r0 = blockIdx.x * 64;
    for (int i = tid; i < 64*FI; i += 256)
        sx[i >> 7][i & 127] = x[(size_t)(r0 + (i >> 7))*FI + (i & 127)];
    __syncthreads();
    int col = tid & 63;
    float accv[16];
    int cnt = 0;
    for (int rr = tid >> 6; rr < 64; rr += 4) {
        float acc = 0.f;
        #pragma unroll
        for (int k = 0; k < FI; k++) acc += sx[rr][k] * sW[k*FO + col];
        g_h[(size_t)(r0 + rr)*FO + col] = acc;
        accv[cnt++] = acc;
    }
    __syncthreads();
    float* sh = sW;
    cnt = 0;
    for (int rr = tid >> 6; rr < 64; rr += 4) sh[rr*64 + col] = accv[cnt++];
    __syncthreads();
    int w = tid >> 5, lane = tid & 31;
    for (int rr = w * 8; rr < w * 8 + 8; rr++) {
        float h0 = sh[rr*64 + lane];
        float h1 = sh[rr*64 + 32 + lane];
        float s = h0 * a[lane]      + h1 * a[lane + 32];
        float t = h0 * a[lane + 64] + h1 * a[lane + 96];
        #pragma unroll
        for (int o = 16; o; o >>= 1) {
            s += __shfl_xor_sync(0xffffffffu, s, o);
            t += __shfl_xor_sync(0xffffffffu, t, o);
        }
        if (lane == 0) {
            int gi = r0 + rr;
            g_s[gi] = s; g_t[gi] = t;
            g_p[gi] = expf(s); g_q[gi] = expf(LRALPHA * s);
            g_u[gi] = expf(t); g_v[gi] = expf(LRALPHA * t);
        }
    }
}

// -------- kernel 2: bf16 hi/lo split of h, N-major --------
__global__ void k_tables() {
    int n = blockIdx.y;                       // 0..NBF-1
    int j = blockIdx.x * 256 + threadIdx.x;
    float base = g_h[(size_t)j*FO + n];
    __nv_bfloat16 bh = __float2bfloat16(base);
    size_t o = (size_t)n*NN + j;
    g_Bh[o] = bh;
    g_Bl[o] = __float2bfloat16(base - __bfloat162float(bh));
}

// ---------------- kernel 3: merged-branch HMMA masked GEMM ----------------
// SMEM: s/p/q 1.5K(pad 2K) | WH 16K | WL 16K | B 2 stages x 2 streams x 8192
#define SM_SS    0
#define SM_WH    2048
#define A_BYTES  (MT*128)                    // 16384
#define SM_WL    (SM_WH + A_BYTES)
#define SM_B     (SM_WL + A_BYTES)           // 34816
#define B_BYTES  (NBF*128)                   // 8192
#define BSTG     (2*B_BYTES)                 // 16384
#define SM_TOTAL (SM_B + 2*BSTG)             // 67584

__global__ void __launch_bounds__(256, 3) k_main_tc(const int* __restrict__ adj) {
    extern __shared__ char smem[];
    uint32_t sb = smem_u32(smem);
    int tid = threadIdx.x, w = tid >> 5, lane = tid & 31;
    int wm = w & 3, wn = w >> 2;                 // 4 M-groups x 2 N-groups
    int i0 = blockIdx.x * MT;
    int sp = blockIdx.y;
    int jbase = sp * (NN / KSPLIT);
    const int nTiles = (NN / KSPLIT) / KT;       // 16

    float* s_s = (float*)(smem + SM_SS);         // [128]
    float* s_p = s_s + 128;
    float* s_q = s_s + 256;
    if (tid < MT) {
        s_s[tid] = g_s[i0 + tid];
        s_p[tid] = g_p[i0 + tid];
        s_q[tid] = g_q[i0 + tid];
    }

    float acc[2][4][4];
    #pragma unroll
    for (int mt = 0; mt < 2; mt++)
        #pragma unroll
        for (int nb = 0; nb < 4; nb++)
            #pragma unroll
            for (int e = 0; e < 4; e++) acc[mt][nb][e] = 0.f;
    float rsum[8];
    #pragma unroll
    for (int it = 0; it < 8; it++) rsum[it] = 0.f;

    int nbBase = wn * 4;
    uint32_t aRowByte = (uint32_t)(wm * 32 + (lane & 15)) * 128;
    uint32_t aKHalf   = ((lane >> 4) & 1) * 16;
    uint32_t bByte    = (uint32_t)(lane & 7) * 128 + ((lane >> 3) & 1) * 16
                      + ((lane >> 4) & 1) * 1024;

    auto prefetchB = [&](int tt, int st) {
        int j0 = jbase + tt * KT;
        uint32_t bdst = sb + SM_B + st * BSTG;
        for (int v = tid; v < NBF * 8; v += 256) {
            int n = v >> 3, ch = v & 7;
            uint32_t so = SWZ((uint32_t)(n * 128 + ch * 16));
            size_t src = (size_t)n * NN + j0 + ch * 8;
            cp16(bdst + so,           g_Bh + src);
            cp16(bdst + B_BYTES + so, g_Bl + src);
        }
    };

    prefetchB(0, 0);
    CP_COMMIT();

    // this thread's fixed (row, seg) for the build phase: 4 edges per iter
    int bseg = tid & 15;                  // j sub-segment (4 ints)
    int brow = tid >> 4;                  // + it*16
    const int* adjBase = adj + (size_t)(i0 + brow) * NN + bseg * 4;

    for (int t = 0; t < nTiles; t++) {
        int st = t & 1;
        int j0 = jbase + t * KT;
        __syncthreads();     // prior MMA done reading W tiles and B stage (1-st)

        // ---- build W hi/lo bf16 tiles (128 x 64, SW128) + fp32 rowsum ----
        #pragma unroll
        for (int it = 0; it < 8; it++) {
            int r = it * 16 + brow;
            int jc = j0 + bseg * 4;
            int4 av = __ldg((const int4*)(adjBase + (size_t)it * 16 * NN + j0));
            float4 t4 = *(const float4*)(g_t + jc);
            float4 u4 = *(const float4*)(g_u + jc);
            float4 v4 = *(const float4*)(g_v + jc);
            float sr = s_s[r], pr_ = s_p[r], qr_ = s_q[r];
            float w0 = (av.x > 0) ? ((sr + t4.x > 0.f) ? pr_ * u4.x : qr_ * v4.x) : 0.f;
            float w1 = (av.y > 0) ? ((sr + t4.y > 0.f) ? pr_ * u4.y : qr_ * v4.y) : 0.f;
            float w2 = (av.z > 0) ? ((sr + t4.z > 0.f) ? pr_ * u4.z : qr_ * v4.z) : 0.f;
            float w3 = (av.w > 0) ? ((sr + t4.w > 0.f) ? pr_ * u4.w : qr_ * v4.w) : 0.f;
            // fp32 rowsum across the 16 lanes sharing this row
            float loc = (w0 + w1) + (w2 + w3);
            loc += __shfl_xor_sync(0xffffffffu, loc, 1);
            loc += __shfl_xor_sync(0xffffffffu, loc, 2);
            loc += __shfl_xor_sync(0xffffffffu, loc, 4);
            loc += __shfl_xor_sync(0xffffffffu, loc, 8);
            rsum[it] += loc;
            uint2 H, L;
            packpair(H.x, L.x, w0, w1);
            packpair(H.y, L.y, w2, w3);
            uint32_t boff = SWZ((uint32_t)(r * 128 + bseg * 8));
            *(uint2*)(smem + SM_WH + boff) = H;
            *(uint2*)(smem + SM_WL + boff) = L;
        }

        if (t + 1 < nTiles) {
            prefetchB(t + 1, 1 - st);
            CP_COMMIT();
            CP_WAIT(1);
        } else {
            CP_WAIT(0);
        }
        __syncthreads();

        // prefetch next tile's adj into L1 (one 128B line per thread)
        if (t + 1 < nTiles)
            prefetchL1(adj + (size_t)(i0 + (tid >> 1)) * NN + (j0 + KT) + (tid & 1) * 32);

        // ---- MMA phase: 4 ksteps, 3 streams ----
        uint32_t bbase = sb + SM_B + st * BSTG;
        #pragma unroll
        for (int ks = 0; ks < 4; ks++) {
            uint32_t kB = (uint32_t)ks * 32;
            uint32_t aH[2][4], aL[2][4];
            #pragma unroll
            for (int mt = 0; mt < 2; mt++) {
                uint32_t aoff = SWZ(aRowByte + mt * 2048u + kB + aKHalf);
                ldm_x4(sb + SM_WH + aoff, aH[mt]);
                ldm_x4(sb + SM_WL + aoff, aL[mt]);
            }
            #pragma unroll
            for (int pr = 0; pr < 2; pr++) {
                uint32_t boff = SWZ(bByte + (nbBase + 2 * pr) * 1024u + kB);
                uint32_t bh[4], bl[4];
                ldm_x4(bbase + boff, bh);
                ldm_x4(bbase + B_BYTES + boff, bl);
                mma16816(acc[0][2*pr],   aH[0], bh);
                mma16816(acc[1][2*pr],   aH[1], bh);
                mma16816(acc[0][2*pr+1], aH[0], bh + 2);
                mma16816(acc[1][2*pr+1], aH[1], bh + 2);
                mma16816(acc[0][2*pr],   aL[0], bh);
                mma16816(acc[1][2*pr],   aL[1], bh);
                mma16816(acc[0][2*pr+1], aL[0], bh + 2);
                mma16816(acc[1][2*pr+1], aL[1], bh + 2);
                mma16816(acc[0][2*pr],   aH[0], bl);
                mma16816(acc[1][2*pr],   aH[1], bl);
                mma16816(acc[0][2*pr+1], aH[0], bl + 2);
                mma16816(acc[1][2*pr+1], aH[1], bl + 2);
            }
        }
    }

    // ---- epilogue: fp32 partials; den from build-phase rowsum ----
    int gp = lane >> 2, tg = lane & 3;
    #pragma unroll
    for (int mt = 0; mt < 2; mt++) {
        int row0 = i0 + wm * 32 + mt * 16 + gp;
        #pragma unroll
        for (int nb = 0; nb < 4; nb++) {
            int col = (nbBase + nb) * 8 + tg * 2;
            size_t o0 = (size_t)row0 * STRIDE_OUT + col;
            size_t o1 = (size_t)(row0 + 8) * STRIDE_OUT + col;
            g_num[sp][o0]     = acc[mt][nb][0];
            g_num[sp][o0 + 1] = acc[mt][nb][1];
            g_num[sp][o1]     = acc[mt][nb][2];
            g_num[sp][o1 + 1] = acc[mt][nb][3];
        }
    }
    if ((tid & 15) == 0) {
        #pragma unroll
        for (int it = 0; it < 8; it++) {
            int row = i0 + it * 16 + brow;
            g_num[sp][(size_t)row * STRIDE_OUT + 64] = rsum[it];
        }
    }
}

// ---------------- kernel 4: combine splits, divide, ELU ----------------
__global__ void k_final(float* __restrict__ out) {
    int idx = blockIdx.x * 256 + threadIdx.x;
    int i = idx >> 6, c = idx & 63;
    size_t b = (size_t)i * STRIDE_OUT;
    float num = 0.f, den = 0.f;
    #pragma unroll
    for (int s2 = 0; s2 < KSPLIT; s2++) {
        num += g_num[s2][b + c];
        den += g_num[s2][b + 64];
    }
    float hv = num / den;
    out[idx] = hv > 0.f ? hv : expm1f(hv);
}

extern "C" void kernel_launch(void* const* d_in, const int* in_sizes, int n_in,
                              void* d_out, int out_size) {
    const float* x   = (const float*)d_in[0];
    const int*   adj = (const int*)  d_in[1];
    const float* W   = (const float*)d_in[2];
    const float* a   = (const float*)d_in[3];
    float* out = (float*)d_out;

    cudaFuncSetAttribute(k_main_tc, cudaFuncAttributeMaxDynamicSharedMemorySize, SM_TOTAL);

    k_gemm_h<<<NN/64, 256>>>(x, W, a);
    dim3 gt(NN/256, NBF);
    k_tables<<<gt, 256>>>();
    dim3 gm(NN/MT, KSPLIT);
    k_main_tc<<<gm, 256, SM_TOTAL>>>(adj);
    k_final<<<(NN*FO)/256, 256>>>(out);
}

// round 11
// speedup vs baseline: 1.1791x; 1.1791x over previous
#include <cuda_runtime.h>
#include <cuda_bf16.h>
#include <cstdint>

#define NN 8192
#define FI 128
#define FO 64
#define LRALPHA 0.2f
#define KSPLIT 4
#define MT 128          // M rows per CTA
#define KT 64           // j per K-tile
#define NBF 64          // B rows (features only; den via build rowsum)
#define STRIDE_OUT 72

// ---------------- device scratch ----------------
__device__ float g_h[NN*FO];
__device__ __align__(16) float g_t[NN];
__device__ __align__(16) float g_u[NN], g_v[NN];   // fp32 exp(t), exp(a t)
__device__ float g_s[NN], g_p[NN], g_q[NN];
__device__ __align__(16) __nv_bfloat16 g_Bh[(size_t)NBF*NN];  // bf16(h)
__device__ __align__(16) __nv_bfloat16 g_Bl[(size_t)NBF*NN];  // residual
__device__ float g_num[KSPLIT][(size_t)NN*STRIDE_OUT];

// ---------------- helpers ----------------
__device__ __forceinline__ uint32_t smem_u32(const void* p) {
    uint32_t a;
    asm("{ .reg .u64 t; cvta.to.shared.u64 t, %1; cvt.u32.u64 %0, t; }" : "=r"(a) : "l"(p));
    return a;
}
#define SWZ(x) ((uint32_t)(x) ^ ((((uint32_t)(x)) >> 3) & 0x70u))

__device__ __forceinline__ void ldm_x4(uint32_t addr, uint32_t r[4]) {
    asm volatile("ldmatrix.sync.aligned.m8n8.x4.shared.b16 {%0,%1,%2,%3}, [%4];"
        : "=r"(r[0]), "=r"(r[1]), "=r"(r[2]), "=r"(r[3]) : "r"(addr));
}
__device__ __forceinline__ void mma16816(float* c, const uint32_t* a, const uint32_t* b) {
    asm("mma.sync.aligned.m16n8k16.row.col.f32.bf16.bf16.f32 "
        "{%0,%1,%2,%3}, {%4,%5,%6,%7}, {%8,%9}, {%0,%1,%2,%3};"
        : "+f"(c[0]), "+f"(c[1]), "+f"(c[2]), "+f"(c[3])
        : "r"(a[0]), "r"(a[1]), "r"(a[2]), "r"(a[3]), "r"(b[0]), "r"(b[1]));
}
__device__ __forceinline__ void cp16(uint32_t dst, const void* src) {
    asm volatile("cp.async.cg.shared.global [%0], [%1], 16;" :: "r"(dst), "l"(src) : "memory");
}
#define CP_COMMIT() asm volatile("cp.async.commit_group;" ::: "memory")
#define CP_WAIT(n)  asm volatile("cp.async.wait_group %0;" :: "n"(n) : "memory")
__device__ __forceinline__ void prefetchL1(const void* p) {
    asm volatile("prefetch.global.L1 [%0];" :: "l"(p));
}

// pack two fp32 weights into hi-bf16x2 and lo-bf16x2 (truncation split)
__device__ __forceinline__ void packpair(uint32_t& hi, uint32_t& lo, float w0, float w1) {
    uint32_t b0 = __float_as_uint(w0), b1 = __float_as_uint(w1);
    hi = __byte_perm(b0, b1, 0x7632);
    float l0 = w0 - __uint_as_float(b0 & 0xFFFF0000u);
    float l1 = w1 - __uint_as_float(b1 & 0xFFFF0000u);
    lo = __byte_perm(__float_as_uint(l0), __float_as_uint(l1), 0x7632);
}

// ---------------- kernel 1: h = x @ W  (+ fused per-row scalars) ----------------
__global__ void k_gemm_h(const float* __restrict__ x, const float* __restrict__ W,
                         const float* __restrict__ a) {
    __shared__ float sW[FI*FO];     // reused as sh[64][64]
    __shared__ float sx[64][FI];
    int tid = threadIdx.x;
    for (int i = tid; i < FI*FO; i += 256) sW[i] = W[i];
    int r0 = blockIdx.x * 64;
    for (int i = tid; i < 64*FI; i += 256)
        sx[i >> 7][i & 127] = x[(size_t)(r0 + (i >> 7))*FI + (i & 127)];
    __syncthreads();
    int col = tid & 63;
    float accv[16];
    int cnt = 0;
    for (int rr = tid >> 6; rr < 64; rr += 4) {
        float acc = 0.f;
        #pragma unroll
        for (int k = 0; k < FI; k++) acc += sx[rr][k] * sW[k*FO + col];
        g_h[(size_t)(r0 + rr)*FO + col] = acc;
        accv[cnt++] = acc;
    }
    __syncthreads();
    float* sh = sW;
    cnt = 0;
    for (int rr = tid >> 6; rr < 64; rr += 4) sh[rr*64 + col] = accv[cnt++];
    __syncthreads();
    int w = tid >> 5, lane = tid & 31;
    for (int rr = w * 8; rr < w * 8 + 8; rr++) {
        float h0 = sh[rr*64 + lane];
        float h1 = sh[rr*64 + 32 + lane];
        float s = h0 * a[lane]      + h1 * a[lane + 32];
        float t = h0 * a[lane + 64] + h1 * a[lane + 96];
        #pragma unroll
        for (int o = 16; o; o >>= 1) {
            s += __shfl_xor_sync(0xffffffffu, s, o);
            t += __shfl_xor_sync(0xffffffffu, t, o);
        }
        if (lane == 0) {
            int gi = r0 + rr;
            g_s[gi] = s; g_t[gi] = t;
            g_p[gi] = expf(s); g_q[gi] = expf(LRALPHA * s);
            g_u[gi] = expf(t); g_v[gi] = expf(LRALPHA * t);
        }
    }
}

// -------- kernel 2: bf16 hi/lo split of h, N-major --------
__global__ void k_tables() {
    int n = blockIdx.y;                       // 0..NBF-1
    int j = blockIdx.x * 256 + threadIdx.x;
    float base = g_h[(size_t)j*FO + n];
    __nv_bfloat16 bh = __float2bfloat16(base);
    size_t o = (size_t)n*NN + j;
    g_Bh[o] = bh;
    g_Bl[o] = __float2bfloat16(base - __bfloat162float(bh));
}

// ---------------- kernel 3: merged-branch HMMA masked GEMM ----------------
// SMEM: s/p/q 1.5K(pad 2K) | WH 16K | WL 16K | B 2 stages x 2 streams x 8192
#define SM_SS    0
#define SM_WH    2048
#define A_BYTES  (MT*128)                    // 16384
#define SM_WL    (SM_WH + A_BYTES)
#define SM_B     (SM_WL + A_BYTES)           // 34816
#define B_BYTES  (NBF*128)                   // 8192
#define BSTG     (2*B_BYTES)                 // 16384
#define SM_TOTAL (SM_B + 2*BSTG)             // 67584

__global__ void __launch_bounds__(256, 2) k_main_tc(const int* __restrict__ adj) {
    extern __shared__ char smem[];
    uint32_t sb = smem_u32(smem);
    int tid = threadIdx.x, w = tid >> 5, lane = tid & 31;
    int wm = w & 3, wn = w >> 2;                 // 4 M-groups x 2 N-groups
    int i0 = blockIdx.x * MT;
    int sp = blockIdx.y;
    int jbase = sp * (NN / KSPLIT);
    const int nTiles = (NN / KSPLIT) / KT;       // 32

    float* s_s = (float*)(smem + SM_SS);         // [128]
    float* s_p = s_s + 128;
    float* s_q = s_s + 256;
    if (tid < MT) {
        s_s[tid] = g_s[i0 + tid];
        s_p[tid] = g_p[i0 + tid];
        s_q[tid] = g_q[i0 + tid];
    }

    float acc[2][4][4];
    #pragma unroll
    for (int mt = 0; mt < 2; mt++)
        #pragma unroll
        for (int nb = 0; nb < 4; nb++)
            #pragma unroll
            for (int e = 0; e < 4; e++) acc[mt][nb][e] = 0.f;
    float rsum[4] = {0.f, 0.f, 0.f, 0.f};

    int nbBase = wn * 4;
    uint32_t aRowByte = (uint32_t)(wm * 32 + (lane & 15)) * 128;
    uint32_t aKHalf   = ((lane >> 4) & 1) * 16;
    uint32_t bByte    = (uint32_t)(lane & 7) * 128 + ((lane >> 3) & 1) * 16
                      + ((lane >> 4) & 1) * 1024;

    // build-phase fixed coordinates: seg (8-j segment) and row base
    int seg   = tid & 7;          // j segment of 8
    int rbase = tid >> 3;         // 0..31; row = it*32 + rbase

    auto prefetchB = [&](int tt, int st) {
        int j0 = jbase + tt * KT;
        uint32_t bdst = sb + SM_B + st * BSTG;
        for (int v = tid; v < NBF * 8; v += 256) {
            int n = v >> 3, ch = v & 7;
            uint32_t so = SWZ((uint32_t)(n * 128 + ch * 16));
            size_t src = (size_t)n * NN + j0 + ch * 8;
            cp16(bdst + so,           g_Bh + src);
            cp16(bdst + B_BYTES + so, g_Bl + src);
        }
    };

    prefetchB(0, 0);
    CP_COMMIT();

    for (int t = 0; t < nTiles; t++) {
        int st = t & 1;
        int j0 = jbase + t * KT;
        __syncthreads();     // prior MMA done reading W tiles and B stage (1-st)

        // ---- build W hi/lo bf16 tiles (128 x 64, SW128) + fp32 rowsum ----
        {
            int jc = j0 + seg * 8;
            float4 t0 = *(const float4*)(g_t + jc);
            float4 t1 = *(const float4*)(g_t + jc + 4);
            float4 u0 = *(const float4*)(g_u + jc);
            float4 u1 = *(const float4*)(g_u + jc + 4);
            float4 v0 = *(const float4*)(g_v + jc);
            float4 v1 = *(const float4*)(g_v + jc + 4);
            #pragma unroll
            for (int it = 0; it < 4; it++) {
                int r = it * 32 + rbase;
                const int* ap = adj + (size_t)(i0 + r) * NN + jc;
                int4 a0 = __ldg((const int4*)ap);
                int4 a1 = __ldg((const int4*)(ap + 4));
                float sr = s_s[r], pr_ = s_p[r], qr_ = s_q[r];
                float w0 = (a0.x > 0) ? ((sr + t0.x > 0.f) ? pr_ * u0.x : qr_ * v0.x) : 0.f;
                float w1 = (a0.y > 0) ? ((sr + t0.y > 0.f) ? pr_ * u0.y : qr_ * v0.y) : 0.f;
                float w2 = (a0.z > 0) ? ((sr + t0.z > 0.f) ? pr_ * u0.z : qr_ * v0.z) : 0.f;
                float w3 = (a0.w > 0) ? ((sr + t0.w > 0.f) ? pr_ * u0.w : qr_ * v0.w) : 0.f;
                float w4 = (a1.x > 0) ? ((sr + t1.x > 0.f) ? pr_ * u1.x : qr_ * v1.x) : 0.f;
                float w5 = (a1.y > 0) ? ((sr + t1.y > 0.f) ? pr_ * u1.y : qr_ * v1.y) : 0.f;
                float w6 = (a1.z > 0) ? ((sr + t1.z > 0.f) ? pr_ * u1.z : qr_ * v1.z) : 0.f;
                float w7 = (a1.w > 0) ? ((sr + t1.w > 0.f) ? pr_ * u1.w : qr_ * v1.w) : 0.f;
                rsum[it] += ((w0 + w1) + (w2 + w3)) + ((w4 + w5) + (w6 + w7));
                uint4 H, L;
                packpair(H.x, L.x, w0, w1);
                packpair(H.y, L.y, w2, w3);
                packpair(H.z, L.z, w4, w5);
                packpair(H.w, L.w, w6, w7);
                uint32_t boff = SWZ((uint32_t)(r * 128 + seg * 16));
                *(uint4*)(smem + SM_WH + boff) = H;
                *(uint4*)(smem + SM_WL + boff) = L;
            }
        }

        if (t + 1 < nTiles) {
            prefetchB(t + 1, 1 - st);
            CP_COMMIT();
            CP_WAIT(1);
        } else {
            CP_WAIT(0);
        }
        __syncthreads();

        // prefetch next tile's adj into L1 (one 128B line per thread)
        if (t + 1 < nTiles)
            prefetchL1(adj + (size_t)(i0 + (tid >> 1)) * NN + (j0 + KT) + (tid & 1) * 32);

        // ---- MMA phase: 4 ksteps, 3 streams ----
        uint32_t bbase = sb + SM_B + st * BSTG;
        #pragma unroll
        for (int ks = 0; ks < 4; ks++) {
            uint32_t kB = (uint32_t)ks * 32;
            uint32_t aH[2][4], aL[2][4];
            #pragma unroll
            for (int mt = 0; mt < 2; mt++) {
                uint32_t aoff = SWZ(aRowByte + mt * 2048u + kB + aKHalf);
                ldm_x4(sb + SM_WH + aoff, aH[mt]);
                ldm_x4(sb + SM_WL + aoff, aL[mt]);
            }
            #pragma unroll
            for (int pr = 0; pr < 2; pr++) {
                uint32_t boff = SWZ(bByte + (nbBase + 2 * pr) * 1024u + kB);
                uint32_t bh[4], bl[4];
                ldm_x4(bbase + boff, bh);
                ldm_x4(bbase + B_BYTES + boff, bl);
                mma16816(acc[0][2*pr],   aH[0], bh);
                mma16816(acc[1][2*pr],   aH[1], bh);
                mma16816(acc[0][2*pr+1], aH[0], bh + 2);
                mma16816(acc[1][2*pr+1], aH[1], bh + 2);
                mma16816(acc[0][2*pr],   aL[0], bh);
                mma16816(acc[1][2*pr],   aL[1], bh);
                mma16816(acc[0][2*pr+1], aL[0], bh + 2);
                mma16816(acc[1][2*pr+1], aL[1], bh + 2);
                mma16816(acc[0][2*pr],   aH[0], bl);
                mma16816(acc[1][2*pr],   aH[1], bl);
                mma16816(acc[0][2*pr+1], aH[0], bl + 2);
                mma16816(acc[1][2*pr+1], aH[1], bl + 2);
            }
        }
    }

    // ---- epilogue: fp32 partials; den via deferred 8-lane reduction ----
    #pragma unroll
    for (int it = 0; it < 4; it++) {
        float rv = rsum[it];
        rv += __shfl_xor_sync(0xffffffffu, rv, 1);
        rv += __shfl_xor_sync(0xffffffffu, rv, 2);
        rv += __shfl_xor_sync(0xffffffffu, rv, 4);
        if (seg == 0)
            g_num[sp][(size_t)(i0 + it * 32 + rbase) * STRIDE_OUT + 64] = rv;
    }
    int gp = lane >> 2, tg = lane & 3;
    #pragma unroll
    for (int mt = 0; mt < 2; mt++) {
        int row0 = i0 + wm * 32 + mt * 16 + gp;
        #pragma unroll
        for (int nb = 0; nb < 4; nb++) {
            int col = (nbBase + nb) * 8 + tg * 2;
            size_t o0 = (size_t)row0 * STRIDE_OUT + col;
            size_t o1 = (size_t)(row0 + 8) * STRIDE_OUT + col;
            g_num[sp][o0]     = acc[mt][nb][0];
            g_num[sp][o0 + 1] = acc[mt][nb][1];
            g_num[sp][o1]     = acc[mt][nb][2];
            g_num[sp][o1 + 1] = acc[mt][nb][3];
        }
    }
}

// ---------------- kernel 4: combine splits, divide, ELU ----------------
__global__ void k_final(float* __restrict__ out) {
    int idx = blockIdx.x * 256 + threadIdx.x;
    int i = idx >> 6, c = idx & 63;
    size_t b = (size_t)i * STRIDE_OUT;
    float num = 0.f, den = 0.f;
    #pragma unroll
    for (int s2 = 0; s2 < KSPLIT; s2++) {
        num += g_num[s2][b + c];
        den += g_num[s2][b + 64];
    }
    float hv = num / den;
    out[idx] = hv > 0.f ? hv : expm1f(hv);
}

extern "C" void kernel_launch(void* const* d_in, const int* in_sizes, int n_in,
                              void* d_out, int out_size) {
    const float* x   = (const float*)d_in[0];
    const int*   adj = (const int*)  d_in[1];
    const float* W   = (const float*)d_in[2];
    const float* a   = (const float*)d_in[3];
    float* out = (float*)d_out;

    cudaFuncSetAttribute(k_main_tc, cudaFuncAttributeMaxDynamicSharedMemorySize, SM_TOTAL);

    k_gemm_h<<<NN/64, 256>>>(x, W, a);
    dim3 gt(NN/256, NBF);
    k_tables<<<gt, 256>>>();
    dim3 gm(NN/MT, KSPLIT);
    k_main_tc<<<gm, 256, SM_TOTAL>>>(adj);
    k_final<<<(NN*FO)/256, 256>>>(out);
}

// round 12
// speedup vs baseline: 1.2097x; 1.0259x over previous
#include <cuda_runtime.h>
#include <cuda_bf16.h>
#include <cstdint>

#define NN 8192
#define FI 128
#define FO 64
#define LRALPHA 0.2f
#define KSPLIT 4
#define MT 128          // M rows per CTA
#define KT 64           // j per K-tile
#define NBF 64          // B rows (features only; den via build rowsum)
#define STRIDE_OUT 72

// ---------------- device scratch ----------------
__device__ float g_h[NN*FO];
__device__ __align__(16) float g_t[NN];
__device__ __align__(16) float g_u[NN], g_v[NN];   // fp32 exp(t), exp(a t)
__device__ float g_s[NN], g_p[NN], g_q[NN];
__device__ __align__(16) __nv_bfloat16 g_Bh[(size_t)NBF*NN];  // bf16(h)
__device__ __align__(16) __nv_bfloat16 g_Bl[(size_t)NBF*NN];  // residual
__device__ float g_num[KSPLIT][(size_t)NN*STRIDE_OUT];

// ---------------- helpers ----------------
__device__ __forceinline__ uint32_t smem_u32(const void* p) {
    uint32_t a;
    asm("{ .reg .u64 t; cvta.to.shared.u64 t, %1; cvt.u32.u64 %0, t; }" : "=r"(a) : "l"(p));
    return a;
}
#define SWZ(x) ((uint32_t)(x) ^ ((((uint32_t)(x)) >> 3) & 0x70u))

__device__ __forceinline__ void ldm_x4(uint32_t addr, uint32_t r[4]) {
    asm volatile("ldmatrix.sync.aligned.m8n8.x4.shared.b16 {%0,%1,%2,%3}, [%4];"
        : "=r"(r[0]), "=r"(r[1]), "=r"(r[2]), "=r"(r[3]) : "r"(addr));
}
__device__ __forceinline__ void mma16816(float* c, const uint32_t* a, const uint32_t* b) {
    asm("mma.sync.aligned.m16n8k16.row.col.f32.bf16.bf16.f32 "
        "{%0,%1,%2,%3}, {%4,%5,%6,%7}, {%8,%9}, {%0,%1,%2,%3};"
        : "+f"(c[0]), "+f"(c[1]), "+f"(c[2]), "+f"(c[3])
        : "r"(a[0]), "r"(a[1]), "r"(a[2]), "r"(a[3]), "r"(b[0]), "r"(b[1]));
}
__device__ __forceinline__ void cp16(uint32_t dst, const void* src) {
    asm volatile("cp.async.cg.shared.global [%0], [%1], 16;" :: "r"(dst), "l"(src) : "memory");
}
#define CP_COMMIT() asm volatile("cp.async.commit_group;" ::: "memory")
#define CP_WAIT(n)  asm volatile("cp.async.wait_group %0;" :: "n"(n) : "memory")
__device__ __forceinline__ void prefetchL1(const void* p) {
    asm volatile("prefetch.global.L1 [%0];" :: "l"(p));
}

// pack two fp32 weights into hi-bf16x2 and lo-bf16x2 (truncation split)
__device__ __forceinline__ void packpair(uint32_t& hi, uint32_t& lo, float w0, float w1) {
    uint32_t b0 = __float_as_uint(w0), b1 = __float_as_uint(w1);
    hi = __byte_perm(b0, b1, 0x7632);
    float l0 = w0 - __uint_as_float(b0 & 0xFFFF0000u);
    float l1 = w1 - __uint_as_float(b1 & 0xFFFF0000u);
    lo = __byte_perm(__float_as_uint(l0), __float_as_uint(l1), 0x7632);
}

// ---------------- kernel 1: h = x @ W  (+ fused per-row scalars) ----------------
__global__ void k_gemm_h(const float* __restrict__ x, const float* __restrict__ W,
                         const float* __restrict__ a) {
    __shared__ float sW[FI*FO];     // reused as sh[64][64]
    __shared__ float sx[64][FI];
    int tid = threadIdx.x;
    for (int i = tid; i < FI*FO; i += 256) sW[i] = W[i];
    int r0 = blockIdx.x * 64;
    for (int i = tid; i < 64*FI; i += 256)
        sx[i >> 7][i & 127] = x[(size_t)(r0 + (i >> 7))*FI + (i & 127)];
    __syncthreads();
    int col = tid & 63;
    float accv[16];
    int cnt = 0;
    for (int rr = tid >> 6; rr < 64; rr += 4) {
        float acc = 0.f;
        #pragma unroll
        for (int k = 0; k < FI; k++) acc += sx[rr][k] * sW[k*FO + col];
        g_h[(size_t)(r0 + rr)*FO + col] = acc;
        accv[cnt++] = acc;
    }
    __syncthreads();
    float* sh = sW;
    cnt = 0;
    for (int rr = tid >> 6; rr < 64; rr += 4) sh[rr*64 + col] = accv[cnt++];
    __syncthreads();
    int w = tid >> 5, lane = tid & 31;
    for (int rr = w * 8; rr < w * 8 + 8; rr++) {
        float h0 = sh[rr*64 + lane];
        float h1 = sh[rr*64 + 32 + lane];
        float s = h0 * a[lane]      + h1 * a[lane + 32];
        float t = h0 * a[lane + 64] + h1 * a[lane + 96];
        #pragma unroll
        for (int o = 16; o; o >>= 1) {
            s += __shfl_xor_sync(0xffffffffu, s, o);
            t += __shfl_xor_sync(0xffffffffu, t, o);
        }
        if (lane == 0) {
            int gi = r0 + rr;
            g_s[gi] = s; g_t[gi] = t;
            g_p[gi] = expf(s); g_q[gi] = expf(LRALPHA * s);
            g_u[gi] = expf(t); g_v[gi] = expf(LRALPHA * t);
        }
    }
}

// -------- kernel 2: bf16 hi/lo split of h, N-major --------
__global__ void k_tables() {
    int n = blockIdx.y;                       // 0..NBF-1
    int j = blockIdx.x * 256 + threadIdx.x;
    float base = g_h[(size_t)j*FO + n];
    __nv_bfloat16 bh = __float2bfloat16(base);
    size_t o = (size_t)n*NN + j;
    g_Bh[o] = bh;
    g_Bl[o] = __float2bfloat16(base - __bfloat162float(bh));
}

// ---------------- kernel 3: pipelined merged-branch HMMA masked GEMM ----------------
// SMEM: s/p/q 2K | W 2 stages x (WH 16K + WL 16K) | B 2 stages x 2 x 8K
#define SM_SS    0
#define SM_W     2048
#define A_BYTES  (MT*128)                    // 16384
#define W_STG    (2*A_BYTES)                 // 32768 (WH then WL)
#define SM_B     (SM_W + 2*W_STG)            // 67584
#define B_BYTES  (NBF*128)                   // 8192
#define BSTG     (2*B_BYTES)                 // 16384
#define SM_TOTAL (SM_B + 2*BSTG)             // 100352

__global__ void __launch_bounds__(256, 2) k_main_tc(const int* __restrict__ adj) {
    extern __shared__ char smem[];
    uint32_t sb = smem_u32(smem);
    int tid = threadIdx.x, w = tid >> 5, lane = tid & 31;
    int wm = w & 3, wn = w >> 2;                 // 4 M-groups x 2 N-groups
    int i0 = blockIdx.x * MT;
    int sp = blockIdx.y;
    int jbase = sp * (NN / KSPLIT);
    const int nTiles = (NN / KSPLIT) / KT;       // 32

    float* s_s = (float*)(smem + SM_SS);         // [128]
    float* s_p = s_s + 128;
    float* s_q = s_s + 256;
    if (tid < MT) {
        s_s[tid] = g_s[i0 + tid];
        s_p[tid] = g_p[i0 + tid];
        s_q[tid] = g_q[i0 + tid];
    }

    float acc[2][4][4];
    #pragma unroll
    for (int mt = 0; mt < 2; mt++)
        #pragma unroll
        for (int nb = 0; nb < 4; nb++)
            #pragma unroll
            for (int e = 0; e < 4; e++) acc[mt][nb][e] = 0.f;
    float rsum[4] = {0.f, 0.f, 0.f, 0.f};

    int nbBase = wn * 4;
    uint32_t aRowByte = (uint32_t)(wm * 32 + (lane & 15)) * 128;
    uint32_t aKHalf   = ((lane >> 4) & 1) * 16;
    uint32_t bByte    = (uint32_t)(lane & 7) * 128 + ((lane >> 3) & 1) * 16
                      + ((lane >> 4) & 1) * 1024;

    // build-phase fixed coordinates
    int seg   = tid & 7;          // j segment of 8
    int rbase = tid >> 3;         // 0..31; row = it*32 + rbase

    auto prefetchB = [&](int tt, int st) {
        int j0 = jbase + tt * KT;
        uint32_t bdst = sb + SM_B + st * BSTG;
        for (int v = tid; v < NBF * 8; v += 256) {
            int n = v >> 3, ch = v & 7;
            uint32_t so = SWZ((uint32_t)(n * 128 + ch * 16));
            size_t src = (size_t)n * NN + j0 + ch * 8;
            cp16(bdst + so,           g_Bh + src);
            cp16(bdst + B_BYTES + so, g_Bl + src);
        }
    };

    // build W(tt) hi/lo tiles into stage st; accumulates rsum
    auto buildW = [&](int tt, int st) {
        int jc = jbase + tt * KT + seg * 8;
        char* wb = smem + SM_W + st * W_STG;
        float4 t0 = *(const float4*)(g_t + jc);
        float4 t1 = *(const float4*)(g_t + jc + 4);
        float4 u0 = *(const float4*)(g_u + jc);
        float4 u1 = *(const float4*)(g_u + jc + 4);
        float4 v0 = *(const float4*)(g_v + jc);
        float4 v1 = *(const float4*)(g_v + jc + 4);
        #pragma unroll
        for (int it = 0; it < 4; it++) {
            int r = it * 32 + rbase;
            const int* ap = adj + (size_t)(i0 + r) * NN + jc;
            int4 a0 = __ldg((const int4*)ap);
            int4 a1 = __ldg((const int4*)(ap + 4));
            float sr = s_s[r], pr_ = s_p[r], qr_ = s_q[r];
            float w0 = (a0.x > 0) ? ((sr + t0.x > 0.f) ? pr_ * u0.x : qr_ * v0.x) : 0.f;
            float w1 = (a0.y > 0) ? ((sr + t0.y > 0.f) ? pr_ * u0.y : qr_ * v0.y) : 0.f;
            float w2 = (a0.z > 0) ? ((sr + t0.z > 0.f) ? pr_ * u0.z : qr_ * v0.z) : 0.f;
            float w3 = (a0.w > 0) ? ((sr + t0.w > 0.f) ? pr_ * u0.w : qr_ * v0.w) : 0.f;
            float w4 = (a1.x > 0) ? ((sr + t1.x > 0.f) ? pr_ * u1.x : qr_ * v1.x) : 0.f;
            float w5 = (a1.y > 0) ? ((sr + t1.y > 0.f) ? pr_ * u1.y : qr_ * v1.y) : 0.f;
            float w6 = (a1.z > 0) ? ((sr + t1.z > 0.f) ? pr_ * u1.z : qr_ * v1.z) : 0.f;
            float w7 = (a1.w > 0) ? ((sr + t1.w > 0.f) ? pr_ * u1.w : qr_ * v1.w) : 0.f;
            rsum[it] += ((w0 + w1) + (w2 + w3)) + ((w4 + w5) + (w6 + w7));
            uint4 H, L;
            packpair(H.x, L.x, w0, w1);
            packpair(H.y, L.y, w2, w3);
            packpair(H.z, L.z, w4, w5);
            packpair(H.w, L.w, w6, w7);
            uint32_t boff = SWZ((uint32_t)(r * 128 + seg * 16));
            *(uint4*)(wb + boff) = H;
            *(uint4*)(wb + A_BYTES + boff) = L;
        }
    };

    prefetchB(0, 0);
    CP_COMMIT();
    __syncthreads();           // s_s/p/q visible
    buildW(0, 0);
    __syncthreads();           // W(0) visible to all warps

    for (int t = 0; t < nTiles; t++) {
        int st = t & 1;

        // issue next B stage, build next W tile (disjoint buffers — no barrier)
        if (t + 1 < nTiles) {
            prefetchB(t + 1, 1 - st);
            CP_COMMIT();
            buildW(t + 1, 1 - st);
            CP_WAIT(1);        // B(t) complete (B(t+1) still in flight)
        } else {
            CP_WAIT(0);
        }

        // prefetch adj for tile t+2 into L1
        if (t + 2 < nTiles)
            prefetchL1(adj + (size_t)(i0 + (tid >> 1)) * NN
                       + (jbase + (t + 2) * KT) + (tid & 1) * 32);

        // ---- MMA(t): 4 ksteps, 3 streams ----
        uint32_t wbase = sb + SM_W + st * W_STG;
        uint32_t bbase = sb + SM_B + st * BSTG;
        #pragma unroll
        for (int ks = 0; ks < 4; ks++) {
            uint32_t kB = (uint32_t)ks * 32;
            uint32_t aH[2][4], aL[2][4];
            #pragma unroll
            for (int mt = 0; mt < 2; mt++) {
                uint32_t aoff = SWZ(aRowByte + mt * 2048u + kB + aKHalf);
                ldm_x4(wbase + aoff, aH[mt]);
                ldm_x4(wbase + A_BYTES + aoff, aL[mt]);
            }
            #pragma unroll
            for (int pr = 0; pr < 2; pr++) {
                uint32_t boff = SWZ(bByte + (nbBase + 2 * pr) * 1024u + kB);
                uint32_t bh[4], bl[4];
                ldm_x4(bbase + boff, bh);
                ldm_x4(bbase + B_BYTES + boff, bl);
                mma16816(acc[0][2*pr],   aH[0], bh);
                mma16816(acc[1][2*pr],   aH[1], bh);
                mma16816(acc[0][2*pr+1], aH[0], bh + 2);
                mma16816(acc[1][2*pr+1], aH[1], bh + 2);
                mma16816(acc[0][2*pr],   aL[0], bh);
                mma16816(acc[1][2*pr],   aL[1], bh);
                mma16816(acc[0][2*pr+1], aL[0], bh + 2);
                mma16816(acc[1][2*pr+1], aL[1], bh + 2);
                mma16816(acc[0][2*pr],   aH[0], bl);
                mma16816(acc[1][2*pr],   aH[1], bl);
                mma16816(acc[0][2*pr+1], aH[0], bl + 2);
                mma16816(acc[1][2*pr+1], aH[1], bl + 2);
            }
        }
        __syncthreads();       // all warps done reading W(st), B(st); next iter may overwrite
    }

    // ---- epilogue: fp32 partials; den via deferred 8-lane reduction ----
    #pragma unroll
    for (int it = 0; it < 4; it++) {
        float rv = rsum[it];
        rv += __shfl_xor_sync(0xffffffffu, rv, 1);
        rv += __shfl_xor_sync(0xffffffffu, rv, 2);
        rv += __shfl_xor_sync(0xffffffffu, rv, 4);
        if (seg == 0)
            g_num[sp][(size_t)(i0 + it * 32 + rbase) * STRIDE_OUT + 64] = rv;
    }
    int gp = lane >> 2, tg = lane & 3;
    #pragma unroll
    for (int mt = 0; mt < 2; mt++) {
        int row0 = i0 + wm * 32 + mt * 16 + gp;
        #pragma unroll
        for (int nb = 0; nb < 4; nb++) {
            int col = (nbBase + nb) * 8 + tg * 2;
            size_t o0 = (size_t)row0 * STRIDE_OUT + col;
            size_t o1 = (size_t)(row0 + 8) * STRIDE_OUT + col;
            g_num[sp][o0]     = acc[mt][nb][0];
            g_num[sp][o0 + 1] = acc[mt][nb][1];
            g_num[sp][o1]     = acc[mt][nb][2];
            g_num[sp][o1 + 1] = acc[mt][nb][3];
        }
    }
}

// ---------------- kernel 4: combine splits, divide, ELU ----------------
__global__ void k_final(float* __restrict__ out) {
    int idx = blockIdx.x * 256 + threadIdx.x;
    int i = idx >> 6, c = idx & 63;
    size_t b = (size_t)i * STRIDE_OUT;
    float num = 0.f, den = 0.f;
    #pragma unroll
    for (int s2 = 0; s2 < KSPLIT; s2++) {
        num += g_num[s2][b + c];
        den += g_num[s2][b + 64];
    }
    float hv = num / den;
    out[idx] = hv > 0.f ? hv : expm1f(hv);
}

extern "C" void kernel_launch(void* const* d_in, const int* in_sizes, int n_in,
                              void* d_out, int out_size) {
    const float* x   = (const float*)d_in[0];
    const int*   adj = (const int*)  d_in[1];
    const float* W   = (const float*)d_in[2];
    const float* a   = (const float*)d_in[3];
    float* out = (float*)d_out;

    cudaFuncSetAttribute(k_main_tc, cudaFuncAttributeMaxDynamicSharedMemorySize, SM_TOTAL);

    k_gemm_h<<<NN/64, 256>>>(x, W, a);
    dim3 gt(NN/256, NBF);
    k_tables<<<gt, 256>>>();
    dim3 gm(NN/MT, KSPLIT);
    k_main_tc<<<gm, 256, SM_TOTAL>>>(adj);
    k_final<<<(NN*FO)/256, 256>>>(out);
}

// round 13
// speedup vs baseline: 1.2502x; 1.0335x over previous
#include <cuda_runtime.h>
#include <cuda_bf16.h>
#include <cstdint>

#define NN 8192
#define FI 128
#define FO 64
#define LRALPHA 0.2f
#define KSPLIT 4
#define MT 128          // M rows per CTA
#define KT 64           // j per K-tile
#define NBF 64          // B rows (features only; den via build rowsum)
#define STRIDE_OUT 72

// ---------------- device scratch ----------------
__device__ __align__(16) float g_t[NN];
__device__ __align__(16) float g_u[NN], g_v[NN];   // fp32 exp(t), exp(a t)
__device__ float g_s[NN], g_p[NN], g_q[NN];
__device__ __align__(16) __nv_bfloat16 g_Bh[(size_t)NBF*NN];  // bf16(h), N-major
__device__ __align__(16) __nv_bfloat16 g_Bl[(size_t)NBF*NN];  // residual
__device__ float g_num[KSPLIT][(size_t)NN*STRIDE_OUT];

// ---------------- helpers ----------------
__device__ __forceinline__ uint32_t smem_u32(const void* p) {
    uint32_t a;
    asm("{ .reg .u64 t; cvta.to.shared.u64 t, %1; cvt.u32.u64 %0, t; }" : "=r"(a) : "l"(p));
    return a;
}
#define SWZ(x) ((uint32_t)(x) ^ ((((uint32_t)(x)) >> 3) & 0x70u))

__device__ __forceinline__ void ldm_x4(uint32_t addr, uint32_t r[4]) {
    asm volatile("ldmatrix.sync.aligned.m8n8.x4.shared.b16 {%0,%1,%2,%3}, [%4];"
        : "=r"(r[0]), "=r"(r[1]), "=r"(r[2]), "=r"(r[3]) : "r"(addr));
}
__device__ __forceinline__ void mma16816(float* c, const uint32_t* a, const uint32_t* b) {
    asm("mma.sync.aligned.m16n8k16.row.col.f32.bf16.bf16.f32 "
        "{%0,%1,%2,%3}, {%4,%5,%6,%7}, {%8,%9}, {%0,%1,%2,%3};"
        : "+f"(c[0]), "+f"(c[1]), "+f"(c[2]), "+f"(c[3])
        : "r"(a[0]), "r"(a[1]), "r"(a[2]), "r"(a[3]), "r"(b[0]), "r"(b[1]));
}
__device__ __forceinline__ void cp16(uint32_t dst, const void* src) {
    asm volatile("cp.async.cg.shared.global [%0], [%1], 16;" :: "r"(dst), "l"(src) : "memory");
}
#define CP_COMMIT() asm volatile("cp.async.commit_group;" ::: "memory")
#define CP_WAIT(n)  asm volatile("cp.async.wait_group %0;" :: "n"(n) : "memory")
__device__ __forceinline__ void prefetchL1(const void* p) {
    asm volatile("prefetch.global.L1 [%0];" :: "l"(p));
}

// pack two fp32 weights into hi-bf16x2 and lo-bf16x2 (truncation split)
__device__ __forceinline__ void packpair(uint32_t& hi, uint32_t& lo, float w0, float w1) {
    uint32_t b0 = __float_as_uint(w0), b1 = __float_as_uint(w1);
    hi = __byte_perm(b0, b1, 0x7632);
    float l0 = w0 - __uint_as_float(b0 & 0xFFFF0000u);
    float l1 = w1 - __uint_as_float(b1 & 0xFFFF0000u);
    lo = __byte_perm(__float_as_uint(l0), __float_as_uint(l1), 0x7632);
}

// ---- kernel 1: h = x @ W, fused per-row scalars AND N-major bf16 tables ----
__global__ void k_gemm_h(const float* __restrict__ x, const float* __restrict__ W,
                         const float* __restrict__ a) {
    __shared__ float sW[FI*FO];     // 32KB; reused as sh[64][65] afterwards
    __shared__ float sx[64][FI];    // 32KB
    int tid = threadIdx.x;
    for (int i = tid; i < FI*FO; i += 256) sW[i] = W[i];
    int r0 = blockIdx.x * 64;
    for (int i = tid; i < 64*FI; i += 256)
        sx[i >> 7][i & 127] = x[(size_t)(r0 + (i >> 7))*FI + (i & 127)];
    __syncthreads();
    int col = tid & 63;
    float accv[16];
    int cnt = 0;
    for (int rr = tid >> 6; rr < 64; rr += 4) {
        float acc = 0.f;
        #pragma unroll
        for (int k = 0; k < FI; k++) acc += sx[rr][k] * sW[k*FO + col];
        accv[cnt++] = acc;
    }
    __syncthreads();    // all sW reads done; reuse as padded sh[64][65]
    float* sh = sW;
    cnt = 0;
    for (int rr = tid >> 6; rr < 64; rr += 4) sh[rr*65 + col] = accv[cnt++];
    __syncthreads();
    int w = tid >> 5, lane = tid & 31;
    for (int rr = w * 8; rr < w * 8 + 8; rr++) {
        float h0 = sh[rr*65 + lane];
        float h1 = sh[rr*65 + 32 + lane];
        float s = h0 * a[lane]      + h1 * a[lane + 32];
        float t = h0 * a[lane + 64] + h1 * a[lane + 96];
        #pragma unroll
        for (int o = 16; o; o >>= 1) {
            s += __shfl_xor_sync(0xffffffffu, s, o);
            t += __shfl_xor_sync(0xffffffffu, t, o);
        }
        if (lane == 0) {
            int gi = r0 + rr;
            g_s[gi] = s; g_t[gi] = t;
            g_p[gi] = expf(s); g_q[gi] = expf(LRALPHA * s);
            g_u[gi] = expf(t); g_v[gi] = expf(LRALPHA * t);
        }
    }
    // N-major bf16 hi/lo tables for this 64-row j-slice
    {
        int jj = tid & 63;
        for (int n = tid >> 6; n < FO; n += 4) {
            float base = sh[jj*65 + n];
            __nv_bfloat16 bh = __float2bfloat16(base);
            size_t o = (size_t)n*NN + r0 + jj;
            g_Bh[o] = bh;
            g_Bl[o] = __float2bfloat16(base - __bfloat162float(bh));
        }
    }
}

// ---------------- kernel 2: pipelined merged-branch HMMA masked GEMM ----------------
// SMEM: s/p/q 2K | W 2 stages x (WH 16K + WL 16K) | B 2 stages x 2 x 8K
#define SM_SS    0
#define SM_W     2048
#define A_BYTES  (MT*128)                    // 16384
#define W_STG    (2*A_BYTES)                 // 32768 (WH then WL)
#define SM_B     (SM_W + 2*W_STG)            // 67584
#define B_BYTES  (NBF*128)                   // 8192
#define BSTG     (2*B_BYTES)                 // 16384
#define SM_TOTAL (SM_B + 2*BSTG)             // 100352

__global__ void __launch_bounds__(256, 2) k_main_tc(const int* __restrict__ adj) {
    extern __shared__ char smem[];
    uint32_t sb = smem_u32(smem);
    int tid = threadIdx.x, w = tid >> 5, lane = tid & 31;
    int wm = w & 3, wn = w >> 2;                 // 4 M-groups x 2 N-groups
    int i0 = blockIdx.x * MT;
    int sp = blockIdx.y;
    int jbase = sp * (NN / KSPLIT);
    const int nTiles = (NN / KSPLIT) / KT;       // 32

    float* s_s = (float*)(smem + SM_SS);         // [128]
    float* s_p = s_s + 128;
    float* s_q = s_s + 256;
    if (tid < MT) {
        s_s[tid] = g_s[i0 + tid];
        s_p[tid] = g_p[i0 + tid];
        s_q[tid] = g_q[i0 + tid];
    }

    float acc[2][4][4];
    #pragma unroll
    for (int mt = 0; mt < 2; mt++)
        #pragma unroll
        for (int nb = 0; nb < 4; nb++)
            #pragma unroll
            for (int e = 0; e < 4; e++) acc[mt][nb][e] = 0.f;
    float rsum[4] = {0.f, 0.f, 0.f, 0.f};

    int nbBase = wn * 4;
    uint32_t aRowByte = (uint32_t)(wm * 32 + (lane & 15)) * 128;
    uint32_t aKHalf   = ((lane >> 4) & 1) * 16;
    uint32_t bByte    = (uint32_t)(lane & 7) * 128 + ((lane >> 3) & 1) * 16
                      + ((lane >> 4) & 1) * 1024;

    // build-phase fixed coordinates
    int seg   = tid & 7;          // j segment of 8
    int rbase = tid >> 3;         // 0..31; row = it*32 + rbase

    auto prefetchB = [&](int tt, int st) {
        int j0 = jbase + tt * KT;
        uint32_t bdst = sb + SM_B + st * BSTG;
        for (int v = tid; v < NBF * 8; v += 256) {
            int n = v >> 3, ch = v & 7;
            uint32_t so = SWZ((uint32_t)(n * 128 + ch * 16));
            size_t src = (size_t)n * NN + j0 + ch * 8;
            cp16(bdst + so,           g_Bh + src);
            cp16(bdst + B_BYTES + so, g_Bl + src);
        }
    };

    // build W(tt) hi/lo tiles into stage st; accumulates rsum
    auto buildW = [&](int tt, int st) {
        int jc = jbase + tt * KT + seg * 8;
        char* wb = smem + SM_W + st * W_STG;
        float4 t0 = *(const float4*)(g_t + jc);
        float4 t1 = *(const float4*)(g_t + jc + 4);
        float4 u0 = *(const float4*)(g_u + jc);
        float4 u1 = *(const float4*)(g_u + jc + 4);
        float4 v0 = *(const float4*)(g_v + jc);
        float4 v1 = *(const float4*)(g_v + jc + 4);
        #pragma unroll
        for (int it = 0; it < 4; it++) {
            int r = it * 32 + rbase;
            const int* ap = adj + (size_t)(i0 + r) * NN + jc;
            int4 a0 = __ldg((const int4*)ap);
            int4 a1 = __ldg((const int4*)(ap + 4));
            float sr = s_s[r], pr_ = s_p[r], qr_ = s_q[r];
            float w0 = (a0.x > 0) ? ((sr + t0.x > 0.f) ? pr_ * u0.x : qr_ * v0.x) : 0.f;
            float w1 = (a0.y > 0) ? ((sr + t0.y > 0.f) ? pr_ * u0.y : qr_ * v0.y) : 0.f;
            float w2 = (a0.z > 0) ? ((sr + t0.z > 0.f) ? pr_ * u0.z : qr_ * v0.z) : 0.f;
            float w3 = (a0.w > 0) ? ((sr + t0.w > 0.f) ? pr_ * u0.w : qr_ * v0.w) : 0.f;
            float w4 = (a1.x > 0) ? ((sr + t1.x > 0.f) ? pr_ * u1.x : qr_ * v1.x) : 0.f;
            float w5 = (a1.y > 0) ? ((sr + t1.y > 0.f) ? pr_ * u1.y : qr_ * v1.y) : 0.f;
            float w6 = (a1.z > 0) ? ((sr + t1.z > 0.f) ? pr_ * u1.z : qr_ * v1.z) : 0.f;
            float w7 = (a1.w > 0) ? ((sr + t1.w > 0.f) ? pr_ * u1.w : qr_ * v1.w) : 0.f;
            rsum[it] += ((w0 + w1) + (w2 + w3)) + ((w4 + w5) + (w6 + w7));
            uint4 H, L;
            packpair(H.x, L.x, w0, w1);
            packpair(H.y, L.y, w2, w3);
            packpair(H.z, L.z, w4, w5);
            packpair(H.w, L.w, w6, w7);
            uint32_t boff = SWZ((uint32_t)(r * 128 + seg * 16));
            *(uint4*)(wb + boff) = H;
            *(uint4*)(wb + A_BYTES + boff) = L;
        }
    };

    prefetchB(0, 0);
    CP_COMMIT();
    __syncthreads();           // s_s/p/q visible
    buildW(0, 0);
    __syncthreads();           // W(0) visible to all warps

    for (int t = 0; t < nTiles; t++) {
        int st = t & 1;

        // issue next B stage, build next W tile (disjoint buffers — no barrier)
        if (t + 1 < nTiles) {
            prefetchB(t + 1, 1 - st);
            CP_COMMIT();
            buildW(t + 1, 1 - st);
            CP_WAIT(1);        // B(t) complete (B(t+1) still in flight)
        } else {
            CP_WAIT(0);
        }

        // prefetch adj for tile t+2 into L1
        if (t + 2 < nTiles)
            prefetchL1(adj + (size_t)(i0 + (tid >> 1)) * NN
                       + (jbase + (t + 2) * KT) + (tid & 1) * 32);

        // ---- MMA(t): 4 ksteps, B fragments double-buffered across ksteps ----
        uint32_t wbase = sb + SM_W + st * W_STG;
        uint32_t bbase = sb + SM_B + st * BSTG;
        uint32_t bhB[2][2][4], blB[2][2][4];     // [buf][pr][4]
        #pragma unroll
        for (int pr = 0; pr < 2; pr++) {
            uint32_t boff = SWZ(bByte + (nbBase + 2 * pr) * 1024u);
            ldm_x4(bbase + boff, bhB[0][pr]);
            ldm_x4(bbase + B_BYTES + boff, blB[0][pr]);
        }
        #pragma unroll
        for (int ks = 0; ks < 4; ks++) {
            const int cb = ks & 1;
            uint32_t kB = (uint32_t)ks * 32;
            uint32_t aH[2][4], aL[2][4];
            #pragma unroll
            for (int mt = 0; mt < 2; mt++) {
                uint32_t aoff = SWZ(aRowByte + mt * 2048u + kB + aKHalf);
                ldm_x4(wbase + aoff, aH[mt]);
                ldm_x4(wbase + A_BYTES + aoff, aL[mt]);
            }
            if (ks < 3) {
                uint32_t kBn = kB + 32;
                #pragma unroll
                for (int pr = 0; pr < 2; pr++) {
                    uint32_t boff = SWZ(bByte + (nbBase + 2 * pr) * 1024u + kBn);
                    ldm_x4(bbase + boff, bhB[cb ^ 1][pr]);
                    ldm_x4(bbase + B_BYTES + boff, blB[cb ^ 1][pr]);
                }
            }
            // 24 MMAs in 3 passes of 8 distinct accumulators (RAW gap 8)
            #pragma unroll
            for (int pr = 0; pr < 2; pr++) {
                mma16816(acc[0][2*pr],   aH[0], bhB[cb][pr]);
                mma16816(acc[1][2*pr],   aH[1], bhB[cb][pr]);
                mma16816(acc[0][2*pr+1], aH[0], bhB[cb][pr] + 2);
                mma16816(acc[1][2*pr+1], aH[1], bhB[cb][pr] + 2);
            }
            #pragma unroll
            for (int pr = 0; pr < 2; pr++) {
                mma16816(acc[0][2*pr],   aL[0], bhB[cb][pr]);
                mma16816(acc[1][2*pr],   aL[1], bhB[cb][pr]);
                mma16816(acc[0][2*pr+1], aL[0], bhB[cb][pr] + 2);
                mma16816(acc[1][2*pr+1], aL[1], bhB[cb][pr] + 2);
            }
            #pragma unroll
            for (int pr = 0; pr < 2; pr++) {
                mma16816(acc[0][2*pr],   aH[0], blB[cb][pr]);
                mma16816(acc[1][2*pr],   aH[1], blB[cb][pr]);
                mma16816(acc[0][2*pr+1], aH[0], blB[cb][pr] + 2);
                mma16816(acc[1][2*pr+1], aH[1], blB[cb][pr] + 2);
            }
        }
        __syncthreads();       // all warps done reading W(st), B(st); next iter may overwrite
    }

    // ---- epilogue: fp32 partials; den via deferred 8-lane reduction ----
    #pragma unroll
    for (int it = 0; it < 4; it++) {
        float rv = rsum[it];
        rv += __shfl_xor_sync(0xffffffffu, rv, 1);
        rv += __shfl_xor_sync(0xffffffffu, rv, 2);
        rv += __shfl_xor_sync(0xffffffffu, rv, 4);
        if (seg == 0)
            g_num[sp][(size_t)(i0 + it * 32 + rbase) * STRIDE_OUT + 64] = rv;
    }
    int gp = lane >> 2, tg = lane & 3;
    #pragma unroll
    for (int mt = 0; mt < 2; mt++) {
        int row0 = i0 + wm * 32 + mt * 16 + gp;
        #pragma unroll
        for (int nb = 0; nb < 4; nb++) {
            int col = (nbBase + nb) * 8 + tg * 2;
            size_t o0 = (size_t)row0 * STRIDE_OUT + col;
            size_t o1 = (size_t)(row0 + 8) * STRIDE_OUT + col;
            g_num[sp][o0]     = acc[mt][nb][0];
            g_num[sp][o0 + 1] = acc[mt][nb][1];
            g_num[sp][o1]     = acc[mt][nb][2];
            g_num[sp][o1 + 1] = acc[mt][nb][3];
        }
    }
}

// ---------------- kernel 3: combine splits, divide, ELU ----------------
__global__ void k_final(float* __restrict__ out) {
    int idx = blockIdx.x * 256 + threadIdx.x;
    int i = idx >> 6, c = idx & 63;
    size_t b = (size_t)i * STRIDE_OUT;
    float num = 0.f, den = 0.f;
    #pragma unroll
    for (int s2 = 0; s2 < KSPLIT; s2++) {
        num += g_num[s2][b + c];
        den += g_num[s2][b + 64];
    }
    float hv = num / den;
    out[idx] = hv > 0.f ? hv : expm1f(hv);
}

extern "C" void kernel_launch(void* const* d_in, const int* in_sizes, int n_in,
                              void* d_out, int out_size) {
    const float* x   = (const float*)d_in[0];
    const int*   adj = (const int*)  d_in[1];
    const float* W   = (const float*)d_in[2];
    const float* a   = (const float*)d_in[3];
    float* out = (float*)d_out;

    cudaFuncSetAttribute(k_main_tc, cudaFuncAttributeMaxDynamicSharedMemorySize, SM_TOTAL);

    k_gemm_h<<<NN/64, 256>>>(x, W, a);
    dim3 gm(NN/MT, KSPLIT);
    k_main_tc<<<gm, 256, SM_TOTAL>>>(adj);
    k_final<<<(NN*FO)/256, 256>>>(out);
}

// round 14
// speedup vs baseline: 1.6332x; 1.3064x over previous
#include <cuda_runtime.h>
#include <cuda_bf16.h>
#include <cstdint>

#define NN 8192
#define FI 128
#define FO 64
#define LRALPHA 0.2f
#define KSPLIT 4
#define MT 128          // M rows per CTA
#define KT 64           // j per K-tile
#define NBF 64          // B rows
#define STRIDE_OUT 72

// ---------------- device scratch ----------------
__device__ __align__(16) float g_t[NN];
__device__ __align__(16) float g_u[NN], g_v[NN];   // fp32 exp(t), exp(a t)
__device__ float g_s[NN], g_p[NN], g_q[NN];
__device__ __align__(16) __nv_bfloat16 g_Bh[(size_t)NBF*NN];  // bf16 RN of h, N-major
__device__ float g_num[KSPLIT][(size_t)NN*STRIDE_OUT];

// ---------------- helpers ----------------
__device__ __forceinline__ uint32_t smem_u32(const void* p) {
    uint32_t a;
    asm("{ .reg .u64 t; cvta.to.shared.u64 t, %1; cvt.u32.u64 %0, t; }" : "=r"(a) : "l"(p));
    return a;
}
#define SWZ(x) ((uint32_t)(x) ^ ((((uint32_t)(x)) >> 3) & 0x70u))

__device__ __forceinline__ void ldm_x4(uint32_t addr, uint32_t r[4]) {
    asm volatile("ldmatrix.sync.aligned.m8n8.x4.shared.b16 {%0,%1,%2,%3}, [%4];"
        : "=r"(r[0]), "=r"(r[1]), "=r"(r[2]), "=r"(r[3]) : "r"(addr));
}
__device__ __forceinline__ void mma16816(float* c, const uint32_t* a, const uint32_t* b) {
    asm("mma.sync.aligned.m16n8k16.row.col.f32.bf16.bf16.f32 "
        "{%0,%1,%2,%3}, {%4,%5,%6,%7}, {%8,%9}, {%0,%1,%2,%3};"
        : "+f"(c[0]), "+f"(c[1]), "+f"(c[2]), "+f"(c[3])
        : "r"(a[0]), "r"(a[1]), "r"(a[2]), "r"(a[3]), "r"(b[0]), "r"(b[1]));
}
__device__ __forceinline__ void cp16(uint32_t dst, const void* src) {
    asm volatile("cp.async.cg.shared.global [%0], [%1], 16;" :: "r"(dst), "l"(src) : "memory");
}
#define CP_COMMIT() asm volatile("cp.async.commit_group;" ::: "memory")
#define CP_WAIT(n)  asm volatile("cp.async.wait_group %0;" :: "n"(n) : "memory")
__device__ __forceinline__ void prefetchL1(const void* p) {
    asm volatile("prefetch.global.L1 [%0];" :: "l"(p));
}
__device__ __forceinline__ uint32_t pack_rn(float a, float b) {
    __nv_bfloat162 t = __floats2bfloat162_rn(a, b);   // low = a, high = b
    return *reinterpret_cast<uint32_t*>(&t);
}

// ---- kernel 1: h = x @ W (4x4 reg blocking), fused scalars + bf16 table ----
__global__ void k_gemm_h(const float* __restrict__ x, const float* __restrict__ W,
                         const float* __restrict__ a) {
    __shared__ float sW[FI*FO];       // 32KB; reused as sh[64][65]
    __shared__ float sx[64][132];     // padded: row stride 132 kills bank conflicts
    int tid = threadIdx.x;
    for (int i = tid; i < FI*FO; i += 256) sW[i] = W[i];
    int r0 = blockIdx.x * 64;
    for (int i = tid; i < 64*FI; i += 256)
        sx[i >> 7][i & 127] = x[(size_t)(r0 + (i >> 7))*FI + (i & 127)];
    __syncthreads();
    int c4 = (tid & 15) * 4;
    int r4 = (tid >> 4) * 4;
    float acc4[4][4];
    #pragma unroll
    for (int i = 0; i < 4; i++)
        #pragma unroll
        for (int j = 0; j < 4; j++) acc4[i][j] = 0.f;
    #pragma unroll 4
    for (int k = 0; k < FI; k += 4) {
        float4 xv[4], wv[4];
        #pragma unroll
        for (int i = 0; i < 4; i++) xv[i] = *(const float4*)&sx[r4 + i][k];
        #pragma unroll
        for (int j = 0; j < 4; j++) wv[j] = *(const float4*)&sW[(k + j)*FO + c4];
        #pragma unroll
        for (int i = 0; i < 4; i++) {
            acc4[i][0] += xv[i].x*wv[0].x + xv[i].y*wv[1].x + xv[i].z*wv[2].x + xv[i].w*wv[3].x;
            acc4[i][1] += xv[i].x*wv[0].y + xv[i].y*wv[1].y + xv[i].z*wv[2].y + xv[i].w*wv[3].y;
            acc4[i][2] += xv[i].x*wv[0].z + xv[i].y*wv[1].z + xv[i].z*wv[2].z + xv[i].w*wv[3].z;
            acc4[i][3] += xv[i].x*wv[0].w + xv[i].y*wv[1].w + xv[i].z*wv[2].w + xv[i].w*wv[3].w;
        }
    }
    __syncthreads();    // all sW reads done; reuse as padded sh[64][65]
    float* sh = sW;
    #pragma unroll
    for (int i = 0; i < 4; i++)
        #pragma unroll
        for (int j = 0; j < 4; j++)
            sh[(r4 + i)*65 + c4 + j] = acc4[i][j];
    __syncthreads();
    int w = tid >> 5, lane = tid & 31;
    for (int rr = w * 8; rr < w * 8 + 8; rr++) {
        float h0 = sh[rr*65 + lane];
        float h1 = sh[rr*65 + 32 + lane];
        float s = h0 * a[lane]      + h1 * a[lane + 32];
        float t = h0 * a[lane + 64] + h1 * a[lane + 96];
        #pragma unroll
        for (int o = 16; o; o >>= 1) {
            s += __shfl_xor_sync(0xffffffffu, s, o);
            t += __shfl_xor_sync(0xffffffffu, t, o);
        }
        if (lane == 0) {
            int gi = r0 + rr;
            g_s[gi] = s; g_t[gi] = t;
            g_p[gi] = expf(s); g_q[gi] = expf(LRALPHA * s);
            g_u[gi] = expf(t); g_v[gi] = expf(LRALPHA * t);
        }
    }
    // N-major bf16 RN table for this 64-row j-slice
    {
        int jj = tid & 63;
        for (int n = tid >> 6; n < FO; n += 4)
            g_Bh[(size_t)n*NN + r0 + jj] = __float2bfloat16(sh[jj*65 + n]);
    }
}

// ---------------- kernel 2: single-stream pipelined HMMA masked GEMM ----------------
// SMEM: s/p/q 2K | W 2 stages x 16K | B 2 stages x 8K = 51200
#define SM_SS    0
#define SM_W     2048
#define A_BYTES  (MT*128)                    // 16384
#define W_STG    A_BYTES
#define SM_B     (SM_W + 2*W_STG)            // 34816
#define B_BYTES  (NBF*128)                   // 8192
#define BSTG     B_BYTES
#define SM_TOTAL (SM_B + 2*BSTG)             // 51200

__global__ void __launch_bounds__(256, 2) k_main_tc(const int* __restrict__ adj) {
    extern __shared__ char smem[];
    uint32_t sb = smem_u32(smem);
    int tid = threadIdx.x, w = tid >> 5, lane = tid & 31;
    int wm = w & 3, wn = w >> 2;                 // 4 M-groups x 2 N-groups
    int i0 = blockIdx.x * MT;
    int sp = blockIdx.y;
    int jbase = sp * (NN / KSPLIT);
    const int nTiles = (NN / KSPLIT) / KT;       // 32

    float* s_s = (float*)(smem + SM_SS);         // [128]
    float* s_p = s_s + 128;
    float* s_q = s_s + 256;
    if (tid < MT) {
        s_s[tid] = g_s[i0 + tid];
        s_p[tid] = g_p[i0 + tid];
        s_q[tid] = g_q[i0 + tid];
    }

    float acc[2][4][4];
    #pragma unroll
    for (int mt = 0; mt < 2; mt++)
        #pragma unroll
        for (int nb = 0; nb < 4; nb++)
            #pragma unroll
            for (int e = 0; e < 4; e++) acc[mt][nb][e] = 0.f;
    float rsum[4] = {0.f, 0.f, 0.f, 0.f};

    int nbBase = wn * 4;
    uint32_t aRowByte = (uint32_t)(wm * 32 + (lane & 15)) * 128;
    uint32_t aKHalf   = ((lane >> 4) & 1) * 16;
    uint32_t bByte    = (uint32_t)(lane & 7) * 128 + ((lane >> 3) & 1) * 16
                      + ((lane >> 4) & 1) * 1024;

    // build-phase fixed coordinates
    int seg   = tid & 7;          // j segment of 8
    int rbase = tid >> 3;         // 0..31; row = it*32 + rbase

    auto prefetchB = [&](int tt, int st) {
        int j0 = jbase + tt * KT;
        uint32_t bdst = sb + SM_B + st * BSTG;
        for (int v = tid; v < NBF * 8; v += 256) {
            int n = v >> 3, ch = v & 7;
            cp16(bdst + SWZ((uint32_t)(n * 128 + ch * 16)),
                 g_Bh + (size_t)n * NN + j0 + ch * 8);
        }
    };

    // build W(tt) bf16-RN tile into stage st; accumulates fp32 rowsum
    auto buildW = [&](int tt, int st) {
        int jc = jbase + tt * KT + seg * 8;
        char* wb = smem + SM_W + st * W_STG;
        float4 t0 = *(const float4*)(g_t + jc);
        float4 t1 = *(const float4*)(g_t + jc + 4);
        float4 u0 = *(const float4*)(g_u + jc);
        float4 u1 = *(const float4*)(g_u + jc + 4);
        float4 v0 = *(const float4*)(g_v + jc);
        float4 v1 = *(const float4*)(g_v + jc + 4);
        #pragma unroll
        for (int it = 0; it < 4; it++) {
            int r = it * 32 + rbase;
            const int* ap = adj + (size_t)(i0 + r) * NN + jc;
            int4 a0 = __ldg((const int4*)ap);
            int4 a1 = __ldg((const int4*)(ap + 4));
            float sr = s_s[r], pr_ = s_p[r], qr_ = s_q[r];
            float w0 = (a0.x > 0) ? ((sr + t0.x > 0.f) ? pr_ * u0.x : qr_ * v0.x) : 0.f;
            float w1 = (a0.y > 0) ? ((sr + t0.y > 0.f) ? pr_ * u0.y : qr_ * v0.y) : 0.f;
            float w2 = (a0.z > 0) ? ((sr + t0.z > 0.f) ? pr_ * u0.z : qr_ * v0.z) : 0.f;
            float w3 = (a0.w > 0) ? ((sr + t0.w > 0.f) ? pr_ * u0.w : qr_ * v0.w) : 0.f;
            float w4 = (a1.x > 0) ? ((sr + t1.x > 0.f) ? pr_ * u1.x : qr_ * v1.x) : 0.f;
            float w5 = (a1.y > 0) ? ((sr + t1.y > 0.f) ? pr_ * u1.y : qr_ * v1.y) : 0.f;
            float w6 = (a1.z > 0) ? ((sr + t1.z > 0.f) ? pr_ * u1.z : qr_ * v1.z) : 0.f;
            float w7 = (a1.w > 0) ? ((sr + t1.w > 0.f) ? pr_ * u1.w : qr_ * v1.w) : 0.f;
            rsum[it] += ((w0 + w1) + (w2 + w3)) + ((w4 + w5) + (w6 + w7));
            uint4 H;
            H.x = pack_rn(w0, w1);
            H.y = pack_rn(w2, w3);
            H.z = pack_rn(w4, w5);
            H.w = pack_rn(w6, w7);
            *(uint4*)(wb + SWZ((uint32_t)(r * 128 + seg * 16))) = H;
        }
    };

    prefetchB(0, 0);
    CP_COMMIT();
    __syncthreads();           // s_s/p/q visible
    buildW(0, 0);
    __syncthreads();           // W(0) visible to all warps

    for (int t = 0; t < nTiles; t++) {
        int st = t & 1;

        // issue next B stage, build next W tile (disjoint buffers — no barrier)
        if (t + 1 < nTiles) {
            prefetchB(t + 1, 1 - st);
            CP_COMMIT();
            buildW(t + 1, 1 - st);
            CP_WAIT(1);        // B(t) complete (B(t+1) still in flight)
        } else {
            CP_WAIT(0);
        }

        // prefetch adj for tile t+2 into L1
        if (t + 2 < nTiles)
            prefetchL1(adj + (size_t)(i0 + (tid >> 1)) * NN
                       + (jbase + (t + 2) * KT) + (tid & 1) * 32);

        // ---- MMA(t): 4 ksteps, B fragments double-buffered ----
        uint32_t wbase = sb + SM_W + st * W_STG;
        uint32_t bbase = sb + SM_B + st * BSTG;
        uint32_t bhB[2][2][4];     // [buf][pr][4]
        #pragma unroll
        for (int pr = 0; pr < 2; pr++)
            ldm_x4(bbase + SWZ(bByte + (nbBase + 2 * pr) * 1024u), bhB[0][pr]);
        #pragma unroll
        for (int ks = 0; ks < 4; ks++) {
            const int cb = ks & 1;
            uint32_t kB = (uint32_t)ks * 32;
            uint32_t aH[2][4];
            #pragma unroll
            for (int mt = 0; mt < 2; mt++)
                ldm_x4(wbase + SWZ(aRowByte + mt * 2048u + kB + aKHalf), aH[mt]);
            if (ks < 3) {
                uint32_t kBn = kB + 32;
                #pragma unroll
                for (int pr = 0; pr < 2; pr++)
                    ldm_x4(bbase + SWZ(bByte + (nbBase + 2 * pr) * 1024u + kBn),
                           bhB[cb ^ 1][pr]);
            }
            // 8 MMAs over 8 distinct accumulators (RAW gap 8)
            #pragma unroll
            for (int pr = 0; pr < 2; pr++) {
                mma16816(acc[0][2*pr],   aH[0], bhB[cb][pr]);
                mma16816(acc[1][2*pr],   aH[1], bhB[cb][pr]);
                mma16816(acc[0][2*pr+1], aH[0], bhB[cb][pr] + 2);
                mma16816(acc[1][2*pr+1], aH[1], bhB[cb][pr] + 2);
            }
        }
        __syncthreads();       // all warps done reading W(st), B(st)
    }

    // ---- epilogue: fp32 partials; den via deferred 8-lane reduction ----
    #pragma unroll
    for (int it = 0; it < 4; it++) {
        float rv = rsum[it];
        rv += __shfl_xor_sync(0xffffffffu, rv, 1);
        rv += __shfl_xor_sync(0xffffffffu, rv, 2);
        rv += __shfl_xor_sync(0xffffffffu, rv, 4);
        if (seg == 0)
            g_num[sp][(size_t)(i0 + it * 32 + rbase) * STRIDE_OUT + 64] = rv;
    }
    int gp = lane >> 2, tg = lane & 3;
    #pragma unroll
    for (int mt = 0; mt < 2; mt++) {
        int row0 = i0 + wm * 32 + mt * 16 + gp;
        #pragma unroll
        for (int nb = 0; nb < 4; nb++) {
            int col = (nbBase + nb) * 8 + tg * 2;
            size_t o0 = (size_t)row0 * STRIDE_OUT + col;
            size_t o1 = (size_t)(row0 + 8) * STRIDE_OUT + col;
            g_num[sp][o0]     = acc[mt][nb][0];
            g_num[sp][o0 + 1] = acc[mt][nb][1];
            g_num[sp][o1]     = acc[mt][nb][2];
            g_num[sp][o1 + 1] = acc[mt][nb][3];
        }
    }
}

// ---------------- kernel 3: combine splits, divide, ELU ----------------
__global__ void k_final(float* __restrict__ out) {
    int idx = blockIdx.x * 256 + threadIdx.x;
    int i = idx >> 6, c = idx & 63;
    size_t b = (size_t)i * STRIDE_OUT;
    float num = 0.f, den = 0.f;
    #pragma unroll
    for (int s2 = 0; s2 < KSPLIT; s2++) {
        num += g_num[s2][b + c];
        den += g_num[s2][b + 64];
    }
    float hv = num / den;
    out[idx] = hv > 0.f ? hv : expm1f(hv);
}

extern "C" void kernel_launch(void* const* d_in, const int* in_sizes, int n_in,
                              void* d_out, int out_size) {
    const float* x   = (const float*)d_in[0];
    const int*   adj = (const int*)  d_in[1];
    const float* W   = (const float*)d_in[2];
    const float* a   = (const float*)d_in[3];
    float* out = (float*)d_out;

    cudaFuncSetAttribute(k_main_tc, cudaFuncAttributeMaxDynamicSharedMemorySize, SM_TOTAL);

    k_gemm_h<<<NN/64, 256>>>(x, W, a);
    dim3 gm(NN/MT, KSPLIT);
    k_main_tc<<<gm, 256, SM_TOTAL>>>(adj);
    k_final<<<(NN*FO)/256, 256>>>(out);
}